// round 14
// baseline (speedup 1.0000x reference)
#include <cuda_runtime.h>
#include <cstdint>

#define THREADS 512   // 128 query-pairs x 4 candidate-chunks
#define NCHUNK  4
#define QPT     2     // queries per thread

// Packed-fp32x2 helpers (sm_103a). Per-lane .rn rounding is bit-identical to
// scalar ops, preserving argmin bit-exactness vs the JAX reference.
#define MUL2(d, a, b) \
    asm("mul.rn.f32x2 %0, %1, %2;" : "=l"(d) : "l"(a), "l"(b))
#define ADD2(d, a, b) \
    asm("add.rn.f32x2 %0, %1, %2;" : "=l"(d) : "l"(a), "l"(b))
#define FMA2(d, a, b, c) \
    asm("fma.rn.f32x2 %0, %1, %2, %3;" : "=l"(d) : "l"(a), "l"(b), "l"(c))

__device__ __forceinline__ unsigned long long pack2(float lo, float hi) {
    unsigned long long r;
    asm("mov.b64 %0, {%1, %2};" : "=l"(r) : "f"(lo), "f"(hi));
    return r;
}
__device__ __forceinline__ void unpack2(float& lo, float& hi,
                                        unsigned long long v) {
    asm("mov.b64 {%0, %1}, %2;" : "=f"(lo), "=f"(hi) : "l"(v));
}

// Chamfer distance, both directions fused via blockIdx.z.
// Candidates cached in smem in pair-SoA layout as ulonglong2 quads:
//   sh2[2p]   = ((x0,x1),(y0,y1))
//   sh2[2p+1] = ((z0,z1),(w0,w1))   w = |c|^2 with reference rounding
// Each thread owns TWO queries and scans one of 4 candidate chunks (2048).
//
// NEW vs R5: the 4 warps that share a chunk start their scan at rotated
// offsets (0/512/1024/1536) so their LDS bursts and min-tree dependency
// bubbles interleave across the SMSP instead of stalling in phase.
// Block tracking is made order-independent: on exact block-min ties the
// SMALLEST block index wins, so results are bit-identical to ascending order.
__global__ __launch_bounds__(THREADS, 1)
void chamfer_kernel(const float* __restrict__ xyz1,
                    const float* __restrict__ xyz2,
                    float* __restrict__ out,
                    int N, int M, int B) {
    extern __shared__ float4 sh[];
    __shared__ float2 red[QPT][THREADS];   // per-query-slot (best, idx)

    const int dir = blockIdx.z;
    const int b   = blockIdx.y;

    const float* q;
    const float* c;
    int Nq, Nc;
    float* dist_out;
    float* idx_out;
    if (dir == 0) {
        q = xyz1; c = xyz2; Nq = N; Nc = M;
        dist_out = out;                                        // dist1
        idx_out  = out + (size_t)B * (N + M);                  // idx1
    } else {
        q = xyz2; c = xyz1; Nq = M; Nc = N;
        dist_out = out + (size_t)B * N;                        // dist2
        idx_out  = out + (size_t)B * (N + M) + (size_t)B * N;  // idx2
    }

    // ---- fill shared memory (pair layout), reference rounding for |c|^2 ----
    const float* cb = c + (size_t)b * Nc * 3;
    const int npairs = Nc >> 1;
    for (int p = threadIdx.x; p < npairs; p += THREADS) {
        float x0 = cb[6 * p + 0], y0 = cb[6 * p + 1], z0 = cb[6 * p + 2];
        float x1 = cb[6 * p + 3], y1 = cb[6 * p + 4], z1 = cb[6 * p + 5];
        float w0 = __fadd_rn(__fadd_rn(__fmul_rn(x0, x0), __fmul_rn(y0, y0)),
                             __fmul_rn(z0, z0));
        float w1 = __fadd_rn(__fadd_rn(__fmul_rn(x1, x1), __fmul_rn(y1, y1)),
                             __fmul_rn(z1, z1));
        sh[2 * p]     = make_float4(x0, x1, y0, y1);
        sh[2 * p + 1] = make_float4(z0, z1, w0, w1);
    }
    __syncthreads();

    const ulonglong2* sh2 = reinterpret_cast<const ulonglong2*>(sh);

    const int qp    = threadIdx.x & 127;   // query pair (0..127)
    const int chunk = threadIdx.x >> 7;    // candidate chunk (0..3)

    float ax[QPT], ay[QPT], az[QPT], sq[QPT];
    unsigned long long AX[QPT], AY[QPT], AZ[QPT], SQ[QPT];
#pragma unroll
    for (int k = 0; k < QPT; k++) {
        const int lane = QPT * qp + k;
        const int i = lane * gridDim.x + blockIdx.x;   // interleaved, balanced
        const int iq = (i < Nq) ? i : 0;
        const float* qpt = q + ((size_t)b * Nq + iq) * 3;
        ax[k] = qpt[0]; ay[k] = qpt[1]; az[k] = qpt[2];
        sq[k] = __fadd_rn(__fadd_rn(__fmul_rn(ax[k], ax[k]),
                                    __fmul_rn(ay[k], ay[k])),
                          __fmul_rn(az[k], az[k]));
        AX[k] = pack2(ax[k], ax[k]); AY[k] = pack2(ay[k], ay[k]);
        AZ[k] = pack2(az[k], az[k]); SQ[k] = pack2(sq[k], sq[k]);
    }
    const unsigned long long M22 = pack2(-2.0f, -2.0f);

    const int csz   = Nc / NCHUNK;         // 2048
    const int cbase = chunk * csz;
    const int cend  = cbase + csz;

    // Warp-rotated scan start: the 4 warps sharing a chunk begin at different
    // quarters so their dependency bubbles interleave across the SMSP.
    const int wq    = (threadIdx.x >> 5) & 3;       // warp index within group
    const int start = cbase + wq * (csz >> 2);      // csz/4 = 512 (mult of 8)

    float best0 = 3.402823466e38f, best1 = 3.402823466e38f;
    int   bj0 = start, bj1 = start;

    // One 8-candidate block; order-independent tie rule (smallest j wins).
#define BLOCK8(jb)                                                          \
    {                                                                       \
        float e0[8], e1[8];                                                 \
        _Pragma("unroll")                                                   \
        for (int p = 0; p < 4; p++) {                                       \
            ulonglong2 A2 = sh2[(jb) + 2 * p];      /* (x2),(y2) */         \
            ulonglong2 B2 = sh2[(jb) + 2 * p + 1];  /* (z2),(w2) */         \
            unsigned long long t0, t1, t2, s2, r2;                          \
            MUL2(t0, A2.x, AX[0]);                                          \
            FMA2(t1, A2.y, AY[0], t0);                                      \
            FMA2(t2, B2.x, AZ[0], t1);                                      \
            ADD2(s2, SQ[0], B2.y);                                          \
            FMA2(r2, M22, t2, s2);                                          \
            unpack2(e0[2 * p], e0[2 * p + 1], r2);                          \
            MUL2(t0, A2.x, AX[1]);                                          \
            FMA2(t1, A2.y, AY[1], t0);                                      \
            FMA2(t2, B2.x, AZ[1], t1);                                      \
            ADD2(s2, SQ[1], B2.y);                                          \
            FMA2(r2, M22, t2, s2);                                          \
            unpack2(e1[2 * p], e1[2 * p + 1], r2);                          \
        }                                                                   \
        float a01 = fminf(e0[0], e0[1]), a23 = fminf(e0[2], e0[3]);         \
        float a45 = fminf(e0[4], e0[5]), a67 = fminf(e0[6], e0[7]);         \
        float bm0 = fminf(fminf(a01, a23), fminf(a45, a67));                \
        float b01 = fminf(e1[0], e1[1]), b23 = fminf(e1[2], e1[3]);         \
        float b45 = fminf(e1[4], e1[5]), b67 = fminf(e1[6], e1[7]);         \
        float bm1 = fminf(fminf(b01, b23), fminf(b45, b67));                \
        if (bm0 < best0 || (bm0 == best0 && (jb) < bj0)) bj0 = (jb);        \
        best0 = fminf(best0, bm0);                                          \
        if (bm1 < best1 || (bm1 == best1 && (jb) < bj1)) bj1 = (jb);        \
        best1 = fminf(best1, bm1);                                          \
    }

    for (int j = start; j < cend; j += 8) BLOCK8(j);
    for (int j = cbase; j < start; j += 8) BLOCK8(j);
#undef BLOCK8

    // ---- recover index within each winning block (first occurrence) ----
    int kw0 = 0, kw1 = 0;
#pragma unroll
    for (int kk = 7; kk >= 0; kk--) {
        int p = kk >> 1, lane = kk & 1;
        {
            float4 A  = sh[bj0 + 2 * p];
            float4 Bv = sh[bj0 + 2 * p + 1];
            float cx = lane ? A.y  : A.x;
            float cy = lane ? A.w  : A.z;
            float cz = lane ? Bv.y : Bv.x;
            float cw = lane ? Bv.w : Bv.z;
            float cr = fmaf(cz, az[0], fmaf(cy, ay[0], __fmul_rn(cx, ax[0])));
            float ek = fmaf(-2.0f, cr, __fadd_rn(sq[0], cw));
            if (ek == best0) kw0 = kk;  // descending: smallest k survives
        }
        {
            float4 A  = sh[bj1 + 2 * p];
            float4 Bv = sh[bj1 + 2 * p + 1];
            float cx = lane ? A.y  : A.x;
            float cy = lane ? A.w  : A.z;
            float cz = lane ? Bv.y : Bv.x;
            float cw = lane ? Bv.w : Bv.z;
            float cr = fmaf(cz, az[1], fmaf(cy, ay[1], __fmul_rn(cx, ax[1])));
            float ek = fmaf(-2.0f, cr, __fadd_rn(sq[1], cw));
            if (ek == best1) kw1 = kk;
        }
    }

    red[0][threadIdx.x] = make_float2(best0, (float)(bj0 + kw0));
    red[1][threadIdx.x] = make_float2(best1, (float)(bj1 + kw1));
    __syncthreads();

    // ---- merge the 4 chunks; ascending chunk order, strict < keeps the
    //      earliest chunk (smaller candidate index) on exact ties ----------
    if (threadIdx.x < 256) {
        const int l  = threadIdx.x;        // query lane 0..255
        const int qi = l * gridDim.x + blockIdx.x;
        if (qi < Nq) {
            const int ql = l & 1;          // query slot within pair
            const int pp = l >> 1;         // pair id
            float2 r = red[ql][pp];        // chunk 0
#pragma unroll
            for (int cth = 1; cth < NCHUNK; cth++) {
                float2 rc = red[ql][cth * 128 + pp];
                if (rc.x < r.x) r = rc;
            }
            dist_out[(size_t)b * Nq + qi] = r.x;
            idx_out [(size_t)b * Nq + qi] = r.y;
        }
    }
}

extern "C" void kernel_launch(void* const* d_in, const int* in_sizes, int n_in,
                              void* d_out, int out_size) {
    const float* xyz1 = (const float*)d_in[0];
    const float* xyz2 = (const float*)d_in[1];
    float* out = (float*)d_out;

    const int B = 2;
    const int N = in_sizes[0] / (3 * B);
    const int M = in_sizes[1] / (3 * B);
    const int maxNM = (N > M) ? N : M;

    const size_t shmem = (size_t)maxNM * sizeof(float4);  // 128 KB for 8192
    cudaFuncSetAttribute(chamfer_kernel,
                         cudaFuncAttributeMaxDynamicSharedMemorySize,
                         (int)shmem);

    // 37 * 2 * 2 = 148 CTAs: one per SM, queries interleaved for balance.
    dim3 grid(37, B, 2);
    chamfer_kernel<<<grid, THREADS, shmem>>>(xyz1, xyz2, out, N, M, B);
}